// round 17
// baseline (speedup 1.0000x reference)
#include <cuda_runtime.h>
#include <cuda_bf16.h>
#include <cuda_fp16.h>
#include <math.h>
#include <stdint.h>

#define B_   4
#define C_   256
#define CQK_ 128
#define N_   4096

// ---------------- scratch (device globals; no allocations allowed) ----------
__device__ __nv_bfloat16 g_PT[(size_t)B_ * N_ * N_];  // 128 MB [b][j][i] = exp(S^T)
__device__ float g_Linv[B_ * N_];                     // 1 / sum_j exp(S[i][j])
__device__ float g_ps[B_ * 32 * N_];                  // per-tile row sumexp

__device__ __half g_xT[B_ * N_ * C_];     // [b][n][c] fp16
__device__ __half g_wq[CQK_ * C_];
__device__ __half g_wk[CQK_ * C_];
__device__ __half g_wv[C_ * C_];
__device__ __half g_q[B_ * N_ * CQK_];    // [b][n][d] fp16
__device__ __half g_k[B_ * N_ * CQK_];
__device__ __nv_bfloat16 g_v[B_ * C_ * N_];  // [b][c][n] bf16, pre-scaled by Linv

// ---------------- PTX helpers (baseline features only) ----------------------
__device__ __forceinline__ uint32_t smem_u32(const void* p) {
    uint32_t a;
    asm("{ .reg .u64 t; cvta.to.shared.u64 t, %1; cvt.u32.u64 %0, t; }" : "=r"(a) : "l"(p));
    return a;
}
__device__ __forceinline__ void mma_bf16(float* c, const uint32_t* a, const uint32_t* b) {
    asm volatile(
        "mma.sync.aligned.m16n8k16.row.col.f32.bf16.bf16.f32 "
        "{%0,%1,%2,%3}, {%4,%5,%6,%7}, {%8,%9}, {%0,%1,%2,%3};"
        : "+f"(c[0]), "+f"(c[1]), "+f"(c[2]), "+f"(c[3])
        : "r"(a[0]), "r"(a[1]), "r"(a[2]), "r"(a[3]), "r"(b[0]), "r"(b[1]));
}
__device__ __forceinline__ void mma_f16(float* c, const uint32_t* a, const uint32_t* b) {
    asm volatile(
        "mma.sync.aligned.m16n8k16.row.col.f32.f16.f16.f32 "
        "{%0,%1,%2,%3}, {%4,%5,%6,%7}, {%8,%9}, {%0,%1,%2,%3};"
        : "+f"(c[0]), "+f"(c[1]), "+f"(c[2]), "+f"(c[3])
        : "r"(a[0]), "r"(a[1]), "r"(a[2]), "r"(a[3]), "r"(b[0]), "r"(b[1]));
}
__device__ __forceinline__ void ldm_x4(uint32_t* r, uint32_t addr) {
    asm volatile("ldmatrix.sync.aligned.m8n8.x4.shared.b16 {%0,%1,%2,%3}, [%4];"
                 : "=r"(r[0]), "=r"(r[1]), "=r"(r[2]), "=r"(r[3]) : "r"(addr));
}
__device__ __forceinline__ void cp16(uint32_t saddr, const void* g) {
    asm volatile("cp.async.cg.shared.global [%0], [%1], 16;" :: "r"(saddr), "l"(g));
}
#define CP_COMMIT() asm volatile("cp.async.commit_group;" ::: "memory")
#define CP_WAIT0()  asm volatile("cp.async.wait_group 0;" ::: "memory")
#define CP_WAIT1()  asm volatile("cp.async.wait_group 1;" ::: "memory")

// ---------------- staging: 128 rows x 128B (K=64 of 2-byte elems) ------------
template <typename T>
__device__ __forceinline__ void stage64(uint32_t sbase, const T* src, size_t rs,
                                        int kt, int tid) {
    #pragma unroll
    for (int p = 0; p < 4; p++) {
        int idx = p * 256 + tid;
        int row = idx >> 3, c8 = idx & 7;
        uint32_t sa = sbase + row * 128 + ((c8 ^ (row & 7)) << 4);
        cp16(sa, src + (size_t)row * rs + kt + c8 * 8);
    }
}
// 512-thread version
template <typename T>
__device__ __forceinline__ void stage64_512(uint32_t sbase, const T* src, size_t rs,
                                            int kt, int tid) {
    #pragma unroll
    for (int p = 0; p < 2; p++) {
        int idx = p * 512 + tid;
        int row = idx >> 3, c8 = idx & 7;
        uint32_t sa = sbase + row * 128 + ((c8 ^ (row & 7)) << 4);
        cp16(sa, src + (size_t)row * rs + kt + c8 * 8);
    }
}

// ---------------- K=64 chunk, warp tile 64x32 (mi<4) -------------------------
template <bool HALF>
__device__ __forceinline__ void mma_chunk64(float acc[16][4], uint32_t Abase, uint32_t Bbase,
                                            int m_base, int n_base, int lane) {
    const int L7 = lane & 7;
    const int rowA = L7 + (lane & 8);
    const int rowB = L7 + ((lane >> 1) & 8);
    #pragma unroll
    for (int ks = 0; ks < 4; ks++) {
        const int cA = 2 * ks + (lane >> 4);
        const int cB = 2 * ks + ((lane >> 3) & 1);
        const uint32_t swA = (uint32_t)((cA ^ L7) << 4);
        const uint32_t swB = (uint32_t)((cB ^ L7) << 4);

        uint32_t bh[2][4];
        #pragma unroll
        for (int nip = 0; nip < 2; nip++) {
            uint32_t rb = Bbase + (uint32_t)(n_base + nip * 16 + rowB) * 128 + swB;
            ldm_x4(bh[nip], rb);
        }
        #pragma unroll
        for (int mi = 0; mi < 4; mi++) {
            uint32_t ra = Abase + (uint32_t)(m_base + mi * 16 + rowA) * 128 + swA;
            uint32_t a[4];
            ldm_x4(a, ra);
            #pragma unroll
            for (int nip = 0; nip < 2; nip++) {
                #pragma unroll
                for (int h = 0; h < 2; h++) {
                    float* c = acc[mi * 4 + nip * 2 + h];
                    uint32_t bf[2] = {bh[nip][2 * h], bh[nip][2 * h + 1]};
                    if (HALF) mma_f16(c, a, bf);
                    else      mma_bf16(c, a, bf);
                }
            }
        }
    }
}

// ---------------- K=64 chunk, warp tile 32x32 (mi<2) -------------------------
__device__ __forceinline__ void mma_chunk64_s(float acc[8][4], uint32_t Abase, uint32_t Bbase,
                                              int m_base, int n_base, int lane) {
    const int L7 = lane & 7;
    const int rowA = L7 + (lane & 8);
    const int rowB = L7 + ((lane >> 1) & 8);
    #pragma unroll
    for (int ks = 0; ks < 4; ks++) {
        const int cA = 2 * ks + (lane >> 4);
        const int cB = 2 * ks + ((lane >> 3) & 1);
        const uint32_t swA = (uint32_t)((cA ^ L7) << 4);
        const uint32_t swB = (uint32_t)((cB ^ L7) << 4);

        uint32_t bh[2][4];
        #pragma unroll
        for (int nip = 0; nip < 2; nip++) {
            uint32_t rb = Bbase + (uint32_t)(n_base + nip * 16 + rowB) * 128 + swB;
            ldm_x4(bh[nip], rb);
        }
        #pragma unroll
        for (int mi = 0; mi < 2; mi++) {
            uint32_t ra = Abase + (uint32_t)(m_base + mi * 16 + rowA) * 128 + swA;
            uint32_t a[4];
            ldm_x4(a, ra);
            #pragma unroll
            for (int nip = 0; nip < 2; nip++) {
                #pragma unroll
                for (int h = 0; h < 2; h++) {
                    float* c = acc[mi * 4 + nip * 2 + h];
                    uint32_t bf[2] = {bh[nip][2 * h], bh[nip][2 * h + 1]};
                    mma_f16(c, a, bf);
                }
            }
        }
    }
}

// 3-stage K=64 pipeline (32KB/stage), 256 threads
template <int NCH, bool HALF, typename T>
__device__ __forceinline__ void gemm_pipe64(float acc[16][4], uint32_t base,
    const T* A, size_t ars, const T* Bp, size_t brs,
    int m_base, int n_base, int tid, int lane)
{
    stage64(base, A, ars, 0, tid);
    stage64(base + 16384, Bp, brs, 0, tid);
    CP_COMMIT();
    if (NCH > 1) {
        stage64(base + 32768, A, ars, 64, tid);
        stage64(base + 32768 + 16384, Bp, brs, 64, tid);
        CP_COMMIT();
    }
    for (int ch = 0; ch < NCH; ch++) {
        if (ch == NCH - 1) { CP_WAIT0(); } else { CP_WAIT1(); }
        __syncthreads();
        if (ch + 2 < NCH) {
            uint32_t o = (uint32_t)(((ch + 2) % 3) * 32768);
            stage64(base + o, A, ars, (ch + 2) * 64, tid);
            stage64(base + o + 16384, Bp, brs, (ch + 2) * 64, tid);
            CP_COMMIT();
        }
        uint32_t o = (uint32_t)((ch % 3) * 32768);
        mma_chunk64<HALF>(acc, base + o, base + o + 16384, m_base, n_base, lane);
    }
}

// ---------------- kernel 1a: x transpose -> fp16 xT --------------------------
__global__ __launch_bounds__(256) void xsplit(const float* __restrict__ x)
{
    __shared__ float t[32][69];
    const int b  = blockIdx.z;
    const int n0 = blockIdx.x * 64;
    const int c0 = blockIdx.y * 32;
    const float* src = x + (size_t)b * C_ * N_;
    const int tid = threadIdx.x;

    #pragma unroll
    for (int p = 0; p < 2; p++) {
        int idx = p * 256 + tid;
        int row = idx >> 4, col4 = (idx & 15) * 4;
        float4 v = *reinterpret_cast<const float4*>(&src[(size_t)(c0 + row) * N_ + n0 + col4]);
        t[row][col4] = v.x; t[row][col4 + 1] = v.y;
        t[row][col4 + 2] = v.z; t[row][col4 + 3] = v.w;
    }
    __syncthreads();

    const int nn = tid >> 2, cseg = (tid & 3) * 8;
    __align__(16) __half h[8];
    #pragma unroll
    for (int k = 0; k < 8; k++)
        h[k] = __float2half(t[cseg + k][nn]);
    size_t o = ((size_t)b * N_ + n0 + nn) * C_ + c0 + cseg;
    *reinterpret_cast<uint4*>(&g_xT[o]) = *reinterpret_cast<uint4*>(h);
}

// ---------------- kernel 1b: weight -> fp16 ----------------------------------
__global__ __launch_bounds__(256) void wsplit(const float* __restrict__ wq,
                                              const float* __restrict__ wk,
                                              const float* __restrict__ wv)
{
    int i = blockIdx.x * 256 + threadIdx.x;
    if (i < 32768)       g_wq[i]         = __float2half(wq[i]);
    else if (i < 65536)  g_wk[i - 32768] = __float2half(wk[i - 32768]);
    else                 g_wv[i - 65536] = __float2half(wv[i - 65536]);
}

// ---------------- kernel 2a: Q/K projection (single fp16 GEMM) ---------------
__global__ __launch_bounds__(256, 2) void proj_qk_mma(
    const float* __restrict__ bq, const float* __restrict__ bk)
{
    extern __shared__ char dyn[];
    const uint32_t base = smem_u32(dyn);

    const int tid = threadIdx.x;
    const int lane = tid & 31, wid = tid >> 5;
    const int m_base = (wid & 1) * 64, n_base = (wid >> 1) * 32;
    const int g = lane >> 2, q2 = (lane & 3) * 2;

    const int i0 = blockIdx.x * 128;
    const int zy = blockIdx.y;
    const int b = zy & 3;
    const bool isK = zy >= 4;
    const __half* W = isK ? g_wk : g_wq;
    const float* bias = isK ? bk : bq;
    __half* dst = (isK ? g_k : g_q) + ((size_t)b * N_ + i0) * CQK_;

    float acc[16][4] = {};
    gemm_pipe64<4, true>(acc, base,
                         g_xT + ((size_t)b * N_ + i0) * C_, (size_t)C_,
                         W, (size_t)C_, m_base, n_base, tid, lane);

    #pragma unroll
    for (int mi = 0; mi < 4; mi++) {
        #pragma unroll
        for (int ni = 0; ni < 4; ni++) {
            const float* c = acc[mi * 4 + ni];
            const int r = m_base + mi * 16 + g;
            const int col = n_base + ni * 8 + q2;
            float2 bb = *reinterpret_cast<const float2*>(&bias[col]);
            __half2 p0 = __floats2half2_rn(c[0] + bb.x, c[1] + bb.y);
            __half2 p1 = __floats2half2_rn(c[2] + bb.x, c[3] + bb.y);
            *reinterpret_cast<__half2*>(&dst[(size_t)r * CQK_ + col])       = p0;
            *reinterpret_cast<__half2*>(&dst[(size_t)(r + 8) * CQK_ + col]) = p1;
        }
    }
}

// ---------------- kernel 3: scores, persistent over 4 j-tiles ----------------
// smem: Q 2x16384 [0,32768) | K bufs 2x32768 [32768,98304)
//       | ts bf16 [128][136] [98304,133120) | red [133120,135168)
#define SC_Q(d)    (uint32_t)((d) * 16384)
#define SC_K(t, d) (uint32_t)(32768 + (t) * 32768 + (d) * 16384)
#define SC_TS      98304u
#define SC_RED     133120u
#define SC_DYN     135168

__global__ __launch_bounds__(512, 1) void scores_mma()
{
    extern __shared__ char dyn[];
    const uint32_t base = smem_u32(dyn);

    const int tid = threadIdx.x;
    const int lane = tid & 31, wid = tid >> 5;
    const int m_base = (wid & 3) * 32, n_base = (wid >> 2) * 32;
    const int g = lane >> 2, q2 = (lane & 3) * 2;
    const int wn = wid >> 2;

    const int jg = blockIdx.x;              // group of 4 j-tiles
    const int i0 = blockIdx.y * 128, b = blockIdx.z;

    const __half* Q = g_q + ((size_t)b * N_ + i0) * CQK_;
    const __half* K = g_k + ((size_t)b * N_ + jg * 512) * CQK_;

    // stage Q (both K-chunks, persistent) + first K tile; one commit group
    stage64_512(base + SC_Q(0), Q, (size_t)CQK_, 0, tid);
    stage64_512(base + SC_Q(1), Q, (size_t)CQK_, 64, tid);
    stage64_512(base + SC_K(0, 0), K, (size_t)CQK_, 0, tid);
    stage64_512(base + SC_K(0, 1), K, (size_t)CQK_, 64, tid);
    CP_COMMIT();

    __nv_bfloat16* ts = reinterpret_cast<__nv_bfloat16*>(dyn + SC_TS);  // [128][136]
    float* red2 = reinterpret_cast<float*>(dyn + SC_RED);               // [128][4]

    for (int t = 0; t < 4; t++) {
        // prefetch next K tile (other buffer) before consuming current
        if (t < 3) {
            const __half* Kn = K + (size_t)(t + 1) * 128 * CQK_;
            stage64_512(base + SC_K((t + 1) & 1, 0), Kn, (size_t)CQK_, 0, tid);
            stage64_512(base + SC_K((t + 1) & 1, 1), Kn, (size_t)CQK_, 64, tid);
            CP_COMMIT();
            CP_WAIT1();
        } else {
            CP_WAIT0();
        }
        __syncthreads();     // current K visible; prev tile's ts-copy done

        float acc[8][4] = {};
        mma_chunk64_s(acc, base + SC_Q(0), base + SC_K(t & 1, 0), m_base, n_base, lane);
        mma_chunk64_s(acc, base + SC_Q(1), base + SC_K(t & 1, 1), m_base, n_base, lane);

        // exp in place (S bounded; no max subtraction needed)
        #pragma unroll
        for (int u = 0; u < 8; u++)
            #pragma unroll
            for (int v = 0; v < 4; v++)
                acc[u][v] = __expf(acc[u][v]);

        // ---- per-row(i) sumexp partials over this tile's 128 j --------------
        __syncthreads();     // prev combine read of red2 done
        #pragma unroll
        for (int mi = 0; mi < 2; mi++) {
            #pragma unroll
            for (int h = 0; h < 2; h++) {
                const int row = m_base + mi * 16 + h * 8 + g;
                float s = 0.f;
                #pragma unroll
                for (int ni = 0; ni < 4; ni++)
                    s += acc[mi * 4 + ni][2 * h] + acc[mi * 4 + ni][2 * h + 1];
                s += __shfl_xor_sync(0xffffffffu, s, 1);
                s += __shfl_xor_sync(0xffffffffu, s, 2);
                if ((lane & 3) == 0)
                    red2[row * 4 + wn] = s;
            }
        }
        __syncthreads();
        if (tid < 128) {
            float S = red2[tid * 4] + red2[tid * 4 + 1] + red2[tid * 4 + 2] + red2[tid * 4 + 3];
            g_ps[((size_t)b * 32 + jg * 4 + t) * N_ + i0 + tid] = S;
        }
        __syncthreads();

        // ---- transpose (bf16) -> ts[j][i], then coalesced writes ------------
        #pragma unroll
        for (int mi = 0; mi < 2; mi++) {
            #pragma unroll
            for (int ni = 0; ni < 4; ni++) {
                const float* c = acc[mi * 4 + ni];
                const int r = m_base + mi * 16 + g;
                const int col = n_base + ni * 8 + q2;
                ts[col * 136 + r]           = __float2bfloat16(c[0]);
                ts[(col + 1) * 136 + r]     = __float2bfloat16(c[1]);
                ts[col * 136 + r + 8]       = __float2bfloat16(c[2]);
                ts[(col + 1) * 136 + r + 8] = __float2bfloat16(c[3]);
            }
        }
        __syncthreads();
        {
            __nv_bfloat16* dstb = g_PT + ((size_t)b * N_ + jg * 512 + t * 128) * N_ + i0;
            #pragma unroll
            for (int it = 0; it < 8; it++) {
                const int j = wid + it * 16;
                uint2 v = *reinterpret_cast<const uint2*>(&ts[j * 136 + lane * 4]);
                *reinterpret_cast<uint2*>(&dstb[(size_t)j * N_ + lane * 4]) = v;
            }
        }
    }
}

// ---------------- kernel 4: combine partials -> inverse row sums -------------
__global__ __launch_bounds__(256) void inv_combine()
{
    const int idx = blockIdx.x * 256 + threadIdx.x;   // b*N + i
    const int b = idx >> 12, i = idx & 4095;
    const float* ps = g_ps + (size_t)b * 32 * N_ + i;
    float S = 0.f;
    #pragma unroll
    for (int t = 0; t < 32; t++)
        S += ps[(size_t)t * N_];
    g_Linv[idx] = 1.0f / S;
}

// ---------------- kernel 5: V projection (fp16 GEMM), Linv folded ------------
__global__ __launch_bounds__(256, 2) void proj_v_mma(const float* __restrict__ bv)
{
    extern __shared__ char dyn[];
    const uint32_t base = smem_u32(dyn);

    const int tid = threadIdx.x;
    const int lane = tid & 31, wid = tid >> 5;
    const int m_base = (wid & 1) * 64, n_base = (wid >> 1) * 32;
    const int g = lane >> 2, q2 = (lane & 3) * 2;

    const int j0 = blockIdx.x * 128;
    const int c0 = blockIdx.y * 128;
    const int b  = blockIdx.z;

    float acc[16][4] = {};
    gemm_pipe64<4, true>(acc, base,
                         g_wv + (size_t)c0 * C_, (size_t)C_,
                         g_xT + ((size_t)b * N_ + j0) * C_, (size_t)C_,
                         m_base, n_base, tid, lane);

    const float* invb = g_Linv + b * N_ + j0;
    #pragma unroll
    for (int mi = 0; mi < 4; mi++) {
        const int cc = c0 + m_base + mi * 16 + g;
        const float bv0 = bv[cc], bv1 = bv[cc + 8];
        #pragma unroll
        for (int ni = 0; ni < 4; ni++) {
            const float* c = acc[mi * 4 + ni];
            const int col = n_base + ni * 8 + q2;
            float2 iv = *reinterpret_cast<const float2*>(&invb[col]);
            __nv_bfloat162 p0 = __floats2bfloat162_rn((c[0] + bv0) * iv.x, (c[1] + bv0) * iv.y);
            __nv_bfloat162 p1 = __floats2bfloat162_rn((c[2] + bv1) * iv.x, (c[3] + bv1) * iv.y);
            size_t o0 = ((size_t)b * C_ + cc) * N_ + j0 + col;
            size_t o1 = ((size_t)b * C_ + cc + 8) * N_ + j0 + col;
            *reinterpret_cast<__nv_bfloat162*>(&g_v[o0]) = p0;
            *reinterpret_cast<__nv_bfloat162*>(&g_v[o1]) = p1;
        }
    }
}

// ---------------- kernel 6: AV (single bf16 GEMM) + epilogue -----------------
__global__ __launch_bounds__(256, 2) void av_mma(
    const float* __restrict__ x, const float* __restrict__ gamma,
    float* __restrict__ out)
{
    extern __shared__ char dyn[];
    const uint32_t base = smem_u32(dyn);

    const int tid = threadIdx.x;
    const int lane = tid & 31, wid = tid >> 5;
    const int m_base = (wid & 1) * 64, n_base = (wid >> 1) * 32;
    const int g = lane >> 2, q2 = (lane & 3) * 2;

    const int c0 = blockIdx.x * 128, j0 = blockIdx.y * 128, b = blockIdx.z;

    float acc[16][4] = {};
    gemm_pipe64<64, false>(acc, base,
                           g_v + ((size_t)b * C_ + c0) * N_, (size_t)N_,
                           g_PT + ((size_t)b * N_ + j0) * N_, (size_t)N_,
                           m_base, n_base, tid, lane);

    const float gm = gamma[0];
    #pragma unroll
    for (int mi = 0; mi < 4; mi++) {
        #pragma unroll
        for (int ni = 0; ni < 4; ni++) {
            const float* c = acc[mi * 4 + ni];
            const int cc = c0 + m_base + mi * 16 + g;
            const int col = j0 + n_base + ni * 8 + q2;
            size_t o0 = ((size_t)b * C_ + cc) * N_ + col;
            size_t o1 = ((size_t)b * C_ + cc + 8) * N_ + col;
            float2 x0 = *reinterpret_cast<const float2*>(&x[o0]);
            float2 x1 = *reinterpret_cast<const float2*>(&x[o1]);
            *reinterpret_cast<float2*>(&out[o0]) =
                make_float2(gm * c[0] + x0.x, gm * c[1] + x0.y);
            *reinterpret_cast<float2*>(&out[o1]) =
                make_float2(gm * c[2] + x1.x, gm * c[3] + x1.y);
        }
    }
}

// ---------------- launch -----------------------------------------------------
extern "C" void kernel_launch(void* const* d_in, const int* in_sizes, int n_in,
                              void* d_out, int out_size)
{
    const float* x     = (const float*)d_in[0];
    const float* wq    = (const float*)d_in[1];
    const float* bq    = (const float*)d_in[2];
    const float* wk    = (const float*)d_in[3];
    const float* bk    = (const float*)d_in[4];
    const float* wv    = (const float*)d_in[5];
    const float* bv    = (const float*)d_in[6];
    const float* gamma = (const float*)d_in[7];
    float* out = (float*)d_out;

    const int DYN = 98304;   // 3 stages x 32KB
    cudaFuncSetAttribute(proj_qk_mma, cudaFuncAttributeMaxDynamicSharedMemorySize, DYN);
    cudaFuncSetAttribute(proj_v_mma,  cudaFuncAttributeMaxDynamicSharedMemorySize, DYN);
    cudaFuncSetAttribute(scores_mma,  cudaFuncAttributeMaxDynamicSharedMemorySize, SC_DYN);
    cudaFuncSetAttribute(av_mma,      cudaFuncAttributeMaxDynamicSharedMemorySize, DYN);

    xsplit        <<<dim3(N_ / 64, C_ / 32, B_), 256>>>(x);
    wsplit        <<<dim3(512), 256>>>(wq, wk, wv);
    proj_qk_mma   <<<dim3(N_ / 128, B_ * 2), 256, DYN>>>(bq, bk);
    scores_mma    <<<dim3(N_ / 512, N_ / 128, B_), 512, SC_DYN>>>();
    inv_combine   <<<dim3(B_ * N_ / 256), 256>>>();
    proj_v_mma    <<<dim3(N_ / 128, C_ / 128, B_), 256, DYN>>>(bv);
    av_mma        <<<dim3(C_ / 128, N_ / 128, B_), 256, DYN>>>(x, gamma, out);
}